// round 5
// baseline (speedup 1.0000x reference)
#include <cuda_runtime.h>
#include <cuda_bf16.h>
#include <cstdint>
#include <cstddef>

#define BATCH 2
#define SEQ 2048
#define EMB 4096
#define NHEAD 32
#define HDIM 128
#define QKV_COLS (3 * EMB)
#define MROWS (BATCH * SEQ)

// ---------------------------------------------------------------------------
// Scratch (__device__ globals, allocation-free rule)
// ---------------------------------------------------------------------------
__device__ __nv_bfloat16 g_x_hi[(size_t)MROWS * EMB];
__device__ __nv_bfloat16 g_x_lo[(size_t)MROWS * EMB];
__device__ __nv_bfloat16 g_wa_hi[(size_t)QKV_COLS * EMB];  // [N,K] transposed
__device__ __nv_bfloat16 g_wa_lo[(size_t)QKV_COLS * EMB];
__device__ __nv_bfloat16 g_wp_hi[(size_t)EMB * EMB];
__device__ __nv_bfloat16 g_wp_lo[(size_t)EMB * EMB];
__device__ __nv_bfloat16 g_y_hi[(size_t)MROWS * EMB];
__device__ __nv_bfloat16 g_y_lo[(size_t)MROWS * EMB];
// rope-split Q/K/V, [B,S,H,D] bf16
__device__ __nv_bfloat16 g_q_hi[(size_t)MROWS * EMB];
__device__ __nv_bfloat16 g_q_lo[(size_t)MROWS * EMB];
__device__ __nv_bfloat16 g_k_hi[(size_t)MROWS * EMB];
__device__ __nv_bfloat16 g_k_lo[(size_t)MROWS * EMB];
__device__ __nv_bfloat16 g_v_hi[(size_t)MROWS * EMB];
__device__ __nv_bfloat16 g_v_lo[(size_t)MROWS * EMB];

// ---------------------------------------------------------------------------
// PTX helpers (sm_80+ features only: ldmatrix, mma.sync, cp.async)
// ---------------------------------------------------------------------------
__device__ __forceinline__ uint32_t smem_to_u32(const void* smem_ptr) {
    uint32_t addr;
    asm("{ .reg .u64 tmp; cvta.to.shared.u64 tmp, %1; cvt.u32.u64 %0, tmp; }"
        : "=r"(addr) : "l"(smem_ptr));
    return addr;
}

#define SMEM_SWIZZLE_128B(byte_offset) \
    ((byte_offset) ^ (((byte_offset) >> 3) & 0x70))

__device__ __forceinline__ void cp_async16(uint32_t dst, const void* src) {
    asm volatile("cp.async.cg.shared.global [%0], [%1], 16;"
                 :: "r"(dst), "l"(src) : "memory");
}
#define CP_ASYNC_COMMIT() asm volatile("cp.async.commit_group;" ::: "memory")
#define CP_ASYNC_WAIT(n)  asm volatile("cp.async.wait_group %0;" :: "n"(n) : "memory")

#define LDSM_X4(r0, r1, r2, r3, addr) \
    asm volatile("ldmatrix.sync.aligned.m8n8.x4.shared.b16 {%0,%1,%2,%3}, [%4];" \
                 : "=r"(r0), "=r"(r1), "=r"(r2), "=r"(r3) : "r"(addr))

#define LDSM_X4_T(r0, r1, r2, r3, addr) \
    asm volatile("ldmatrix.sync.aligned.m8n8.x4.trans.shared.b16 {%0,%1,%2,%3}, [%4];" \
                 : "=r"(r0), "=r"(r1), "=r"(r2), "=r"(r3) : "r"(addr))

__device__ __forceinline__ void mma16816(float* c, const uint32_t* a,
                                         uint32_t b0, uint32_t b1) {
    asm volatile(
        "mma.sync.aligned.m16n8k16.row.col.f32.bf16.bf16.f32 "
        "{%0,%1,%2,%3}, {%4,%5,%6,%7}, {%8,%9}, {%0,%1,%2,%3};"
        : "+f"(c[0]), "+f"(c[1]), "+f"(c[2]), "+f"(c[3])
        : "r"(a[0]), "r"(a[1]), "r"(a[2]), "r"(a[3]), "r"(b0), "r"(b1));
}

// pack two floats to bf16x2 (first -> low half, second -> high half)
__device__ __forceinline__ uint32_t pack_bf16(float lo, float hi) {
    return (uint32_t)__bfloat16_as_ushort(__float2bfloat16(lo)) |
           ((uint32_t)__bfloat16_as_ushort(__float2bfloat16(hi)) << 16);
}
// split one float into bf16 hi and residual-lo floats
__device__ __forceinline__ void split_hl(float v, float& h, float& l) {
    h = __bfloat162float(__float2bfloat16(v));
    l = v - h;
}

// ---------------------------------------------------------------------------
// Split fp32 -> bf16 hi/lo (elementwise, vectorized)
// ---------------------------------------------------------------------------
__global__ __launch_bounds__(256) void split_f32_kernel(
    const float4* __restrict__ in, uint2* __restrict__ hi, uint2* __restrict__ lo, int n4)
{
    int i = blockIdx.x * 256 + threadIdx.x;
    if (i >= n4) return;
    float4 v = in[i];
    float f[4] = {v.x, v.y, v.z, v.w};
    uint32_t hw[2] = {0, 0}, lw[2] = {0, 0};
#pragma unroll
    for (int j = 0; j < 4; j++) {
        __nv_bfloat16 h = __float2bfloat16(f[j]);
        __nv_bfloat16 l = __float2bfloat16(f[j] - __bfloat162float(h));
        hw[j >> 1] |= ((uint32_t)__bfloat16_as_ushort(h)) << ((j & 1) * 16);
        lw[j >> 1] |= ((uint32_t)__bfloat16_as_ushort(l)) << ((j & 1) * 16);
    }
    hi[i] = make_uint2(hw[0], hw[1]);
    lo[i] = make_uint2(lw[0], lw[1]);
}

// ---------------------------------------------------------------------------
// Split + transpose weights: w [K,N] fp32 (row-major) -> hiT/loT [N,K] bf16
// ---------------------------------------------------------------------------
__global__ __launch_bounds__(256) void split_wT_kernel(
    const float* __restrict__ w, __nv_bfloat16* __restrict__ hiT,
    __nv_bfloat16* __restrict__ loT, int K, int N)
{
    __shared__ float t[32][33];
    const int bx = blockIdx.x;   // N tile
    const int by = blockIdx.y;   // K tile
    const int tx = threadIdx.x;  // 0..31
    const int ty = threadIdx.y;  // 0..7
#pragma unroll
    for (int i = 0; i < 4; i++)
        t[ty + 8 * i][tx] = w[(size_t)(by * 32 + ty + 8 * i) * N + bx * 32 + tx];
    __syncthreads();
#pragma unroll
    for (int i = 0; i < 4; i++) {
        int nn = ty + 8 * i;
        float v = t[tx][nn];
        __nv_bfloat16 h = __float2bfloat16(v);
        __nv_bfloat16 l = __float2bfloat16(v - __bfloat162float(h));
        size_t o = (size_t)(bx * 32 + nn) * K + by * 32 + tx;
        hiT[o] = h;
        loT[o] = l;
    }
}

// ---------------------------------------------------------------------------
// HMMA bf16 split-GEMM, 64x64 warp tiles (FLOP/smem-byte = 32.8).
// CTA tile 128x128, 4 warps (2x2), BK=64, 3-stage cp.async pipeline,
// double-buffered register fragments.
// mode 0: C fp32 output. mode 1 (QKV): fused RoPE + bf16 hi/lo split of
// Q/K/V written to [B,S,H,D] arrays (C unused).
// ---------------------------------------------------------------------------
#define STAGES 3
#define STAGE_BYTES 32768
#define GEMM_SMEM (1024 + STAGES * STAGE_BYTES)

__global__ __launch_bounds__(128) void tc_gemm(
    const __nv_bfloat16* __restrict__ A_hi, const __nv_bfloat16* __restrict__ A_lo,
    const __nv_bfloat16* __restrict__ B_hi, const __nv_bfloat16* __restrict__ B_lo,
    float* __restrict__ C, int M, int N, int K, int mode,
    const float* __restrict__ fcos, const float* __restrict__ fsin,
    __nv_bfloat16* __restrict__ qh, __nv_bfloat16* __restrict__ ql,
    __nv_bfloat16* __restrict__ kh, __nv_bfloat16* __restrict__ kl,
    __nv_bfloat16* __restrict__ vh, __nv_bfloat16* __restrict__ vl)
{
    extern __shared__ char smem_raw[];
    const uint32_t smem_base = smem_to_u32(smem_raw);
    const uint32_t tile_base = (smem_base + 1023) & ~1023u;

    const int tiles_m = M >> 7;
    const int tiles_n = N >> 7;

    // grouped raster for L2 reuse
    const int G = 8;
    int pid = blockIdx.x;
    int npg = G * tiles_n;
    int gid_g = pid / npg;
    int first_m = gid_g * G;
    int gsz = tiles_m - first_m;
    if (gsz > G) gsz = G;
    int pm = first_m + (pid % gsz);
    int pn = (pid % npg) / gsz;
    const int m0 = pm << 7;
    const int n0 = pn << 7;

    const int tid  = threadIdx.x;
    const int wid  = tid >> 5;
    const int lane = tid & 31;

    // ------- loader mapping: thread t = one row of A and one row of B,
    // 8 x 16B column chunks each.
    uint32_t swz[8];
#pragma unroll
    for (int i = 0; i < 8; i++)
        swz[i] = SMEM_SWIZZLE_128B((uint32_t)(tid * 128 + i * 16));
    const size_t aoff = (size_t)(m0 + tid) * K;
    const size_t boff = (size_t)(n0 + tid) * K;

    const __nv_bfloat16* segA[3] = {A_hi, A_hi, A_lo};
    const __nv_bfloat16* segB[3] = {B_hi, B_lo, B_hi};

    const int kc = K >> 6;
    const int n_chunks = 3 * kc;

    // ------- compute mapping: warp grid 2x2, warp tile 64x64
    const int warp_m = wid & 1;
    const int warp_n = wid >> 1;
    const int rA = lane & 15;
    const int cA = lane >> 4;
    const uint32_t xorA = (uint32_t)(rA & 7) << 4;
    const uint32_t rowTermA = (uint32_t)(warp_m * 64 + rA) * 128;
    const int rB = (lane & 7) + ((lane >> 4) & 1) * 8;
    const int cB = (lane >> 3) & 1;
    const uint32_t xorB = (uint32_t)(lane & 7) << 4;
    const uint32_t rowTermB = (uint32_t)(warp_n * 64 + rB) * 128;

    float acc[4][8][4];
#pragma unroll
    for (int mt = 0; mt < 4; mt++)
#pragma unroll
        for (int nt = 0; nt < 8; nt++)
#pragma unroll
            for (int i = 0; i < 4; i++) acc[mt][nt][i] = 0.f;

    auto load_stage = [&](int c) {
        const int s = c % STAGES;
        const int seg = c / kc;
        const int k0 = (c - seg * kc) << 6;
        const __nv_bfloat16* gA = segA[seg] + aoff + k0;
        const __nv_bfloat16* gB = segB[seg] + boff + k0;
        const uint32_t dA = tile_base + s * STAGE_BYTES;
        const uint32_t dB = dA + 16384;
#pragma unroll
        for (int i = 0; i < 8; i++) cp_async16(dA + swz[i], gA + i * 8);
#pragma unroll
        for (int i = 0; i < 8; i++) cp_async16(dB + swz[i], gB + i * 8);
        CP_ASYNC_COMMIT();
    };

    uint32_t af[2][4][4], bfr[2][4][4];
    auto ldfrags = [&](uint32_t sA, uint32_t sB, int kk, int buf) {
#pragma unroll
        for (int mt = 0; mt < 4; mt++) {
            uint32_t addr = sA + rowTermA + mt * 2048 +
                            (((uint32_t)(kk * 2 + cA) << 4) ^ xorA);
            LDSM_X4(af[buf][mt][0], af[buf][mt][1], af[buf][mt][2], af[buf][mt][3], addr);
        }
#pragma unroll
        for (int np = 0; np < 4; np++) {
            uint32_t addr = sB + rowTermB + np * 2048 +
                            (((uint32_t)(kk * 2 + cB) << 4) ^ xorB);
            LDSM_X4(bfr[buf][np][0], bfr[buf][np][1], bfr[buf][np][2], bfr[buf][np][3], addr);
        }
    };

#pragma unroll
    for (int c = 0; c < STAGES - 1; c++) load_stage(c);

    for (int c = 0; c < n_chunks; c++) {
        if (c + 1 < n_chunks) { CP_ASYNC_WAIT(1); } else { CP_ASYNC_WAIT(0); }
        __syncthreads();
        if (c + STAGES - 1 < n_chunks) load_stage(c + STAGES - 1);

        const uint32_t sA = tile_base + (c % STAGES) * STAGE_BYTES;
        const uint32_t sB = sA + 16384;

        ldfrags(sA, sB, 0, 0);
#pragma unroll
        for (int kk = 0; kk < 4; kk++) {
            const int cur = kk & 1;
            if (kk < 3) ldfrags(sA, sB, kk + 1, cur ^ 1);
#pragma unroll
            for (int mt = 0; mt < 4; mt++)
#pragma unroll
                for (int nt = 0; nt < 8; nt++)
                    mma16816(acc[mt][nt], af[cur][mt],
                             bfr[cur][nt >> 1][(nt & 1) * 2],
                             bfr[cur][nt >> 1][(nt & 1) * 2 + 1]);
        }
        __syncthreads();
    }

    // ------- epilogue
    const int egid = lane >> 2;
    const int tig = lane & 3;
    const float ssc = 0.08838834764831845f;  // 1/sqrt(128)

    if (mode == 0) {
#pragma unroll
        for (int mt = 0; mt < 4; mt++) {
#pragma unroll
            for (int nt = 0; nt < 8; nt++) {
                int row = m0 + warp_m * 64 + mt * 16 + egid;
                int col = n0 + warp_n * 64 + nt * 8 + tig * 2;
                *(float2*)(C + (size_t)row * N + col) =
                    make_float2(acc[mt][nt][0], acc[mt][nt][1]);
                *(float2*)(C + (size_t)(row + 8) * N + col) =
                    make_float2(acc[mt][nt][2], acc[mt][nt][3]);
            }
        }
    } else {
        // fused RoPE + bf16 hi/lo split. col layout: [Q|K|V] x (32 heads x 128)
#pragma unroll
        for (int mt = 0; mt < 4; mt++) {
            const int r0 = m0 + warp_m * 64 + mt * 16 + egid;
            const int s0 = r0 & (SEQ - 1);
            const int s1 = (r0 + 8) & (SEQ - 1);
#pragma unroll
            for (int nt = 0; nt < 8; nt++) {
                const int col = n0 + warp_n * 64 + nt * 8 + tig * 2;
                const int qi = col >> 12;          // 0=Q 1=K 2=V
                const int d  = col & 127;
                const int hh = (col >> 7) & 31;
                const int j  = d >> 1;

                float v0 = acc[mt][nt][0], v1 = acc[mt][nt][1];
                float v2 = acc[mt][nt][2], v3 = acc[mt][nt][3];

                if (qi < 2) {
                    const float c0 = fcos[s0 * 64 + j], sn0 = fsin[s0 * 64 + j];
                    const float c1 = fcos[s1 * 64 + j], sn1 = fsin[s1 * 64 + j];
                    const float sc = (qi == 0) ? ssc : 1.f;
                    float o0 = (v0 * c0 - v1 * sn0) * sc;
                    float o1 = (v0 * sn0 + v1 * c0) * sc;
                    float o2 = (v2 * c1 - v3 * sn1) * sc;
                    float o3 = (v2 * sn1 + v3 * c1) * sc;
                    v0 = o0; v1 = o1; v2 = o2; v3 = o3;
                }

                __nv_bfloat16* dh = (qi == 0) ? qh : (qi == 1) ? kh : vh;
                __nv_bfloat16* dl = (qi == 0) ? ql : (qi == 1) ? kl : vl;
                const size_t o0_ = ((size_t)r0 * NHEAD + hh) * HDIM + d;
                const size_t o1_ = o0_ + (size_t)8 * NHEAD * HDIM;

                float h0, l0, h1, l1;
                split_hl(v0, h0, l0); split_hl(v1, h1, l1);
                *(uint32_t*)(dh + o0_) = pack_bf16(h0, h1);
                *(uint32_t*)(dl + o0_) = pack_bf16(l0, l1);
                split_hl(v2, h0, l0); split_hl(v3, h1, l1);
                *(uint32_t*)(dh + o1_) = pack_bf16(h0, h1);
                *(uint32_t*)(dl + o1_) = pack_bf16(l0, l1);
            }
        }
    }
}

// ---------------------------------------------------------------------------
// Tensor-core flash attention (causal). 128 threads = 4 warps, 64 q rows/CTA.
// (unchanged from round 4, verified)
// ---------------------------------------------------------------------------
#define FT_ROWB 272
#define FT_SLOT (64 * FT_ROWB)
#define FT_SMEM (6 * FT_SLOT + 128)

__device__ __forceinline__ void ft_load_tile(
    uint32_t dst, const __nv_bfloat16* __restrict__ g, int grow0, int h, int tid)
{
#pragma unroll
    for (int it = 0; it < 8; it++) {
        int c = tid + it * 128;
        int r = c >> 4, ch = c & 15;
        cp_async16(dst + r * FT_ROWB + ch * 16,
                   g + (size_t)(grow0 + r) * EMB + h * HDIM + ch * 8);
    }
}

__global__ __launch_bounds__(128, 2) void flash_tc(
    const __nv_bfloat16* __restrict__ qh_g, const __nv_bfloat16* __restrict__ ql_g,
    const __nv_bfloat16* __restrict__ kh_g, const __nv_bfloat16* __restrict__ kl_g,
    const __nv_bfloat16* __restrict__ vh_g, const __nv_bfloat16* __restrict__ vl_g,
    __nv_bfloat16* __restrict__ yh_g, __nv_bfloat16* __restrict__ yl_g)
{
    extern __shared__ char sm_raw[];
    const uint32_t base = (smem_to_u32(sm_raw) + 127) & ~127u;
    const uint32_t QH = base, QL = base + FT_SLOT;
    const uint32_t KH = base + 2 * FT_SLOT, KL = base + 3 * FT_SLOT;
    const uint32_t VH = base + 4 * FT_SLOT, VL = base + 5 * FT_SLOT;

    const int tid = threadIdx.x, wid = tid >> 5, lane = tid & 31;
    const int qb = (int)gridDim.x - 1 - (int)blockIdx.x;
    const int bh = blockIdx.y;
    const int b = bh >> 5, h = bh & 31;
    const int q0 = qb * 64;
    const int growq = b * SEQ + q0;

    ft_load_tile(QH, qh_g, growq, h, tid);
    ft_load_tile(QL, ql_g, growq, h, tid);
    CP_ASYNC_COMMIT();
    CP_ASYNC_WAIT(0);
    __syncthreads();

    const int wr = wid * 16;
    const int rA = lane & 15, cA = lane >> 4;
    uint32_t qfh[8][4], qfl[8][4];
#pragma unroll
    for (int kk = 0; kk < 8; kk++) {
        uint32_t ao = (uint32_t)(wr + rA) * FT_ROWB + kk * 32 + cA * 16;
        LDSM_X4(qfh[kk][0], qfh[kk][1], qfh[kk][2], qfh[kk][3], QH + ao);
        LDSM_X4(qfl[kk][0], qfl[kk][1], qfl[kk][2], qfl[kk][3], QL + ao);
    }

    const int rB = (lane & 7) + ((lane >> 4) & 1) * 8;
    const int cB = (lane >> 3) & 1;
    const int vr = lane & 15;
    const int vc = lane >> 4;
    const int egid = lane >> 2, tig = lane & 3;

    float m0 = -1e30f, m1 = -1e30f, l0 = 0.f, l1 = 0.f;
    float accO[16][4];
#pragma unroll
    for (int nt = 0; nt < 16; nt++)
#pragma unroll
        for (int i = 0; i < 4; i++) accO[nt][i] = 0.f;

    for (int t = 0; t <= qb; t++) {
        const int k0 = t * 64;
        const int growk = b * SEQ + k0;
        __syncthreads();
        ft_load_tile(KH, kh_g, growk, h, tid);
        ft_load_tile(KL, kl_g, growk, h, tid);
        ft_load_tile(VH, vh_g, growk, h, tid);
        ft_load_tile(VL, vl_g, growk, h, tid);
        CP_ASYNC_COMMIT();
        CP_ASYNC_WAIT(0);
        __syncthreads();

        float accS[8][4];
#pragma unroll
        for (int nt = 0; nt < 8; nt++)
#pragma unroll
            for (int i = 0; i < 4; i++) accS[nt][i] = 0.f;

#pragma unroll
        for (int kk = 0; kk < 8; kk++) {
            uint32_t bh4[4][4], bl4[4][4];
#pragma unroll
            for (int np = 0; np < 4; np++) {
                uint32_t ao = (uint32_t)(np * 16 + rB) * FT_ROWB + kk * 32 + cB * 16;
                LDSM_X4(bh4[np][0], bh4[np][1], bh4[np][2], bh4[np][3], KH + ao);
                LDSM_X4(bl4[np][0], bl4[np][1], bl4[np][2], bl4[np][3], KL + ao);
            }
#pragma unroll
            for (int np = 0; np < 4; np++)
#pragma unroll
                for (int hf = 0; hf < 2; hf++) {
                    const int nt = np * 2 + hf;
                    mma16816(accS[nt], qfh[kk], bh4[np][hf * 2], bh4[np][hf * 2 + 1]);
                    mma16816(accS[nt], qfl[kk], bh4[np][hf * 2], bh4[np][hf * 2 + 1]);
                    mma16816(accS[nt], qfh[kk], bl4[np][hf * 2], bl4[np][hf * 2 + 1]);
                }
        }

        if (t == qb) {
            const int row0 = wr + egid, row1 = row0 + 8;
#pragma unroll
            for (int nt = 0; nt < 8; nt++) {
                const int c0 = nt * 8 + tig * 2, c1 = c0 + 1;
                if (c0 > row0) accS[nt][0] = -1e30f;
                if (c1 > row0) accS[nt][1] = -1e30f;
                if (c0 > row1) accS[nt][2] = -1e30f;
                if (c1 > row1) accS[nt][3] = -1e30f;
            }
        }

        float mx0 = -1e30f, mx1 = -1e30f;
#pragma unroll
        for (int nt = 0; nt < 8; nt++) {
            mx0 = fmaxf(mx0, fmaxf(accS[nt][0], accS[nt][1]));
            mx1 = fmaxf(mx1, fmaxf(accS[nt][2], accS[nt][3]));
        }
        mx0 = fmaxf(mx0, __shfl_xor_sync(0xffffffffu, mx0, 1));
        mx0 = fmaxf(mx0, __shfl_xor_sync(0xffffffffu, mx0, 2));
        mx1 = fmaxf(mx1, __shfl_xor_sync(0xffffffffu, mx1, 1));
        mx1 = fmaxf(mx1, __shfl_xor_sync(0xffffffffu, mx1, 2));

        const float mn0 = fmaxf(m0, mx0), mn1 = fmaxf(m1, mx1);
        const float a0 = __expf(m0 - mn0), a1 = __expf(m1 - mn1);
        m0 = mn0; m1 = mn1;

        float s0 = 0.f, s1 = 0.f;
#pragma unroll
        for (int nt = 0; nt < 8; nt++) {
            accS[nt][0] = __expf(accS[nt][0] - mn0);
            accS[nt][1] = __expf(accS[nt][1] - mn0);
            accS[nt][2] = __expf(accS[nt][2] - mn1);
            accS[nt][3] = __expf(accS[nt][3] - mn1);
            s0 += accS[nt][0] + accS[nt][1];
            s1 += accS[nt][2] + accS[nt][3];
        }
        s0 += __shfl_xor_sync(0xffffffffu, s0, 1);
        s0 += __shfl_xor_sync(0xffffffffu, s0, 2);
        s1 += __shfl_xor_sync(0xffffffffu, s1, 1);
        s1 += __shfl_xor_sync(0xffffffffu, s1, 2);
        l0 = l0 * a0 + s0;
        l1 = l1 * a1 + s1;

#pragma unroll
        for (int nt = 0; nt < 16; nt++) {
            accO[nt][0] *= a0; accO[nt][1] *= a0;
            accO[nt][2] *= a1; accO[nt][3] *= a1;
        }

        uint32_t pfh[4][4], pfl[4][4];
#pragma unroll
        for (int j = 0; j < 4; j++) {
#pragma unroll
            for (int u = 0; u < 2; u++) {
                const int nt = 2 * j + u;
                float h00, l00, h01, l01, h10, l10, h11, l11;
                split_hl(accS[nt][0], h00, l00);
                split_hl(accS[nt][1], h01, l01);
                split_hl(accS[nt][2], h10, l10);
                split_hl(accS[nt][3], h11, l11);
                pfh[j][u * 2]     = pack_bf16(h00, h01);
                pfh[j][u * 2 + 1] = pack_bf16(h10, h11);
                pfl[j][u * 2]     = pack_bf16(l00, l01);
                pfl[j][u * 2 + 1] = pack_bf16(l10, l11);
            }
        }

#pragma unroll
        for (int j = 0; j < 4; j++) {
#pragma unroll
            for (int np = 0; np < 8; np++) {
                uint32_t vh4[4], vl4[4];
                uint32_t ao = (uint32_t)(j * 16 + vr) * FT_ROWB + np * 32 + vc * 16;
                LDSM_X4_T(vh4[0], vh4[1], vh4[2], vh4[3], VH + ao);
                LDSM_X4_T(vl4[0], vl4[1], vl4[2], vl4[3], VL + ao);
                mma16816(accO[2 * np],     pfh[j], vh4[0], vh4[1]);
                mma16816(accO[2 * np],     pfl[j], vh4[0], vh4[1]);
                mma16816(accO[2 * np],     pfh[j], vl4[0], vl4[1]);
                mma16816(accO[2 * np + 1], pfh[j], vh4[2], vh4[3]);
                mma16816(accO[2 * np + 1], pfl[j], vh4[2], vh4[3]);
                mma16816(accO[2 * np + 1], pfh[j], vl4[2], vl4[3]);
            }
        }
    }

    const float inv0 = 1.f / l0, inv1 = 1.f / l1;
    const size_t row0 = (size_t)(growq + wr + egid);
    const size_t row1 = row0 + 8;
#pragma unroll
    for (int nt = 0; nt < 16; nt++) {
        const int col = h * HDIM + nt * 8 + tig * 2;
        float v0 = accO[nt][0] * inv0, v1 = accO[nt][1] * inv0;
        float v2 = accO[nt][2] * inv1, v3 = accO[nt][3] * inv1;
        float hh, ll, hh2, ll2;
        split_hl(v0, hh, ll); split_hl(v1, hh2, ll2);
        *(uint32_t*)(yh_g + row0 * EMB + col) = pack_bf16(hh, hh2);
        *(uint32_t*)(yl_g + row0 * EMB + col) = pack_bf16(ll, ll2);
        split_hl(v2, hh, ll); split_hl(v3, hh2, ll2);
        *(uint32_t*)(yh_g + row1 * EMB + col) = pack_bf16(hh, hh2);
        *(uint32_t*)(yl_g + row1 * EMB + col) = pack_bf16(ll, ll2);
    }
}

// ---------------------------------------------------------------------------
extern "C" void kernel_launch(void* const* d_in, const int* in_sizes, int n_in,
                              void* d_out, int out_size)
{
    (void)in_sizes; (void)n_in; (void)out_size;
    const float* x       = (const float*)d_in[0];
    const float* w_atten = (const float*)d_in[1];
    const float* w_proj  = (const float*)d_in[2];
    const float* fcos    = (const float*)d_in[3];
    const float* fsin    = (const float*)d_in[4];
    float* out = (float*)d_out;

    __nv_bfloat16 *x_hi, *x_lo, *wa_hi, *wa_lo, *wp_hi, *wp_lo, *y_hi, *y_lo;
    __nv_bfloat16 *q_hi, *q_lo, *k_hi, *k_lo, *v_hi, *v_lo;
    cudaGetSymbolAddress((void**)&x_hi, g_x_hi);
    cudaGetSymbolAddress((void**)&x_lo, g_x_lo);
    cudaGetSymbolAddress((void**)&wa_hi, g_wa_hi);
    cudaGetSymbolAddress((void**)&wa_lo, g_wa_lo);
    cudaGetSymbolAddress((void**)&wp_hi, g_wp_hi);
    cudaGetSymbolAddress((void**)&wp_lo, g_wp_lo);
    cudaGetSymbolAddress((void**)&y_hi, g_y_hi);
    cudaGetSymbolAddress((void**)&y_lo, g_y_lo);
    cudaGetSymbolAddress((void**)&q_hi, g_q_hi);
    cudaGetSymbolAddress((void**)&q_lo, g_q_lo);
    cudaGetSymbolAddress((void**)&k_hi, g_k_hi);
    cudaGetSymbolAddress((void**)&k_lo, g_k_lo);
    cudaGetSymbolAddress((void**)&v_hi, g_v_hi);
    cudaGetSymbolAddress((void**)&v_lo, g_v_lo);

    cudaFuncSetAttribute(tc_gemm, cudaFuncAttributeMaxDynamicSharedMemorySize,
                         GEMM_SMEM);
    cudaFuncSetAttribute(flash_tc, cudaFuncAttributeMaxDynamicSharedMemorySize,
                         FT_SMEM);

    // 1) split x into bf16 hi/lo
    {
        int n4 = MROWS * EMB / 4;
        split_f32_kernel<<<(n4 + 255) / 256, 256>>>(
            (const float4*)x, (uint2*)x_hi, (uint2*)x_lo, n4);
    }
    // 2) split+transpose weights
    split_wT_kernel<<<dim3(QKV_COLS / 32, EMB / 32), dim3(32, 8)>>>(
        w_atten, wa_hi, wa_lo, EMB, QKV_COLS);
    split_wT_kernel<<<dim3(EMB / 32, EMB / 32), dim3(32, 8)>>>(
        w_proj, wp_hi, wp_lo, EMB, EMB);

    // 3) QKV projection + fused RoPE + hi/lo split (HMMA, mode 1)
    tc_gemm<<<(MROWS / 128) * (QKV_COLS / 128), 128, GEMM_SMEM>>>(
        x_hi, x_lo, wa_hi, wa_lo, nullptr, MROWS, QKV_COLS, EMB, 1,
        fcos, fsin, q_hi, q_lo, k_hi, k_lo, v_hi, v_lo);

    // 4) Tensor-core flash attention -> y (bf16 hi/lo)
    {
        dim3 gf(SEQ / 64, BATCH * NHEAD);
        flash_tc<<<gf, 128, FT_SMEM>>>(q_hi, q_lo, k_hi, k_lo, v_hi, v_lo,
                                       y_hi, y_lo);
    }

    // 5) Output projection (HMMA, mode 0)
    tc_gemm<<<(MROWS / 128) * (EMB / 128), 128, GEMM_SMEM>>>(
        y_hi, y_lo, wp_hi, wp_lo, out, MROWS, EMB, EMB, 0,
        nullptr, nullptr, nullptr, nullptr, nullptr, nullptr, nullptr, nullptr);
}

// round 6
// speedup vs baseline: 1.5179x; 1.5179x over previous
#include <cuda_runtime.h>
#include <cuda_bf16.h>
#include <cstdint>
#include <cstddef>

#define BATCH 2
#define SEQ 2048
#define EMB 4096
#define NHEAD 32
#define HDIM 128
#define QKV_COLS (3 * EMB)
#define MROWS (BATCH * SEQ)

// ---------------------------------------------------------------------------
// Scratch (__device__ globals, allocation-free rule)
// ---------------------------------------------------------------------------
__device__ __nv_bfloat16 g_x_hi[(size_t)MROWS * EMB];
__device__ __nv_bfloat16 g_x_lo[(size_t)MROWS * EMB];
__device__ __nv_bfloat16 g_wa_hi[(size_t)QKV_COLS * EMB];  // [N,K] transposed
__device__ __nv_bfloat16 g_wa_lo[(size_t)QKV_COLS * EMB];
__device__ __nv_bfloat16 g_wp_hi[(size_t)EMB * EMB];
__device__ __nv_bfloat16 g_wp_lo[(size_t)EMB * EMB];
__device__ __nv_bfloat16 g_y_hi[(size_t)MROWS * EMB];
__device__ __nv_bfloat16 g_y_lo[(size_t)MROWS * EMB];
// rope-split Q/K/V, [B,S,H,D] bf16
__device__ __nv_bfloat16 g_q_hi[(size_t)MROWS * EMB];
__device__ __nv_bfloat16 g_q_lo[(size_t)MROWS * EMB];
__device__ __nv_bfloat16 g_k_hi[(size_t)MROWS * EMB];
__device__ __nv_bfloat16 g_k_lo[(size_t)MROWS * EMB];
__device__ __nv_bfloat16 g_v_hi[(size_t)MROWS * EMB];
__device__ __nv_bfloat16 g_v_lo[(size_t)MROWS * EMB];

// ---------------------------------------------------------------------------
// PTX helpers (sm_80+ features only: ldmatrix, mma.sync, cp.async)
// ---------------------------------------------------------------------------
__device__ __forceinline__ uint32_t smem_to_u32(const void* smem_ptr) {
    uint32_t addr;
    asm("{ .reg .u64 tmp; cvta.to.shared.u64 tmp, %1; cvt.u32.u64 %0, tmp; }"
        : "=r"(addr) : "l"(smem_ptr));
    return addr;
}

#define SMEM_SWIZZLE_128B(byte_offset) \
    ((byte_offset) ^ (((byte_offset) >> 3) & 0x70))

__device__ __forceinline__ void cp_async16(uint32_t dst, const void* src) {
    asm volatile("cp.async.cg.shared.global [%0], [%1], 16;"
                 :: "r"(dst), "l"(src) : "memory");
}
#define CP_ASYNC_COMMIT() asm volatile("cp.async.commit_group;" ::: "memory")
#define CP_ASYNC_WAIT(n)  asm volatile("cp.async.wait_group %0;" :: "n"(n) : "memory")

#define LDSM_X4(r0, r1, r2, r3, addr) \
    asm volatile("ldmatrix.sync.aligned.m8n8.x4.shared.b16 {%0,%1,%2,%3}, [%4];" \
                 : "=r"(r0), "=r"(r1), "=r"(r2), "=r"(r3) : "r"(addr))

#define LDSM_X4_T(r0, r1, r2, r3, addr) \
    asm volatile("ldmatrix.sync.aligned.m8n8.x4.trans.shared.b16 {%0,%1,%2,%3}, [%4];" \
                 : "=r"(r0), "=r"(r1), "=r"(r2), "=r"(r3) : "r"(addr))

__device__ __forceinline__ void mma16816(float* c, const uint32_t* a,
                                         uint32_t b0, uint32_t b1) {
    asm volatile(
        "mma.sync.aligned.m16n8k16.row.col.f32.bf16.bf16.f32 "
        "{%0,%1,%2,%3}, {%4,%5,%6,%7}, {%8,%9}, {%0,%1,%2,%3};"
        : "+f"(c[0]), "+f"(c[1]), "+f"(c[2]), "+f"(c[3])
        : "r"(a[0]), "r"(a[1]), "r"(a[2]), "r"(a[3]), "r"(b0), "r"(b1));
}

// pack two floats to bf16x2 (first -> low half, second -> high half)
__device__ __forceinline__ uint32_t pack_bf16(float lo, float hi) {
    return (uint32_t)__bfloat16_as_ushort(__float2bfloat16(lo)) |
           ((uint32_t)__bfloat16_as_ushort(__float2bfloat16(hi)) << 16);
}
// split one float into bf16 hi and residual-lo floats
__device__ __forceinline__ void split_hl(float v, float& h, float& l) {
    h = __bfloat162float(__float2bfloat16(v));
    l = v - h;
}

// ---------------------------------------------------------------------------
// Split fp32 -> bf16 hi/lo (elementwise, vectorized)
// ---------------------------------------------------------------------------
__global__ __launch_bounds__(256) void split_f32_kernel(
    const float4* __restrict__ in, uint2* __restrict__ hi, uint2* __restrict__ lo, int n4)
{
    int i = blockIdx.x * 256 + threadIdx.x;
    if (i >= n4) return;
    float4 v = in[i];
    float f[4] = {v.x, v.y, v.z, v.w};
    uint32_t hw[2] = {0, 0}, lw[2] = {0, 0};
#pragma unroll
    for (int j = 0; j < 4; j++) {
        __nv_bfloat16 h = __float2bfloat16(f[j]);
        __nv_bfloat16 l = __float2bfloat16(f[j] - __bfloat162float(h));
        hw[j >> 1] |= ((uint32_t)__bfloat16_as_ushort(h)) << ((j & 1) * 16);
        lw[j >> 1] |= ((uint32_t)__bfloat16_as_ushort(l)) << ((j & 1) * 16);
    }
    hi[i] = make_uint2(hw[0], hw[1]);
    lo[i] = make_uint2(lw[0], lw[1]);
}

// ---------------------------------------------------------------------------
// Split + transpose weights: w [K,N] fp32 (row-major) -> hiT/loT [N,K] bf16
// ---------------------------------------------------------------------------
__global__ __launch_bounds__(256) void split_wT_kernel(
    const float* __restrict__ w, __nv_bfloat16* __restrict__ hiT,
    __nv_bfloat16* __restrict__ loT, int K, int N)
{
    __shared__ float t[32][33];
    const int bx = blockIdx.x;   // N tile
    const int by = blockIdx.y;   // K tile
    const int tx = threadIdx.x;  // 0..31
    const int ty = threadIdx.y;  // 0..7
#pragma unroll
    for (int i = 0; i < 4; i++)
        t[ty + 8 * i][tx] = w[(size_t)(by * 32 + ty + 8 * i) * N + bx * 32 + tx];
    __syncthreads();
#pragma unroll
    for (int i = 0; i < 4; i++) {
        int nn = ty + 8 * i;
        float v = t[tx][nn];
        __nv_bfloat16 h = __float2bfloat16(v);
        __nv_bfloat16 l = __float2bfloat16(v - __bfloat162float(h));
        size_t o = (size_t)(bx * 32 + nn) * K + by * 32 + tx;
        hiT[o] = h;
        loT[o] = l;
    }
}

// ---------------------------------------------------------------------------
// HMMA bf16 split-GEMM. Round-4 geometry (verified 48% tensor):
// CTA tile 128x128, 8 warps (4x2), warp tile 32x64, BK=64, 3-stage cp.async,
// single barrier per chunk. launch_bounds(256,2) pins regs <=128 (2 CTA/SM).
// mode 0: fp32 C.  mode 1 (QKV): fused RoPE + bf16 hi/lo split of Q/K/V.
// ---------------------------------------------------------------------------
#define STAGES 3
#define STAGE_BYTES 32768
#define GEMM_SMEM (1024 + STAGES * STAGE_BYTES)

__global__ __launch_bounds__(256, 2) void tc_gemm(
    const __nv_bfloat16* __restrict__ A_hi, const __nv_bfloat16* __restrict__ A_lo,
    const __nv_bfloat16* __restrict__ B_hi, const __nv_bfloat16* __restrict__ B_lo,
    float* __restrict__ C, int M, int N, int K, int mode,
    const float* __restrict__ fcos, const float* __restrict__ fsin,
    __nv_bfloat16* __restrict__ qh, __nv_bfloat16* __restrict__ ql,
    __nv_bfloat16* __restrict__ kh, __nv_bfloat16* __restrict__ kl,
    __nv_bfloat16* __restrict__ vh, __nv_bfloat16* __restrict__ vl)
{
    extern __shared__ char smem_raw[];
    const uint32_t smem_base = smem_to_u32(smem_raw);
    const uint32_t tile_base = (smem_base + 1023) & ~1023u;

    const int tiles_m = M >> 7;
    const int tiles_n = N >> 7;

    // grouped raster for L2 reuse
    const int G = 8;
    int pid = blockIdx.x;
    int npg = G * tiles_n;
    int gid_g = pid / npg;
    int first_m = gid_g * G;
    int gsz = tiles_m - first_m;
    if (gsz > G) gsz = G;
    int pm = first_m + (pid % gsz);
    int pn = (pid % npg) / gsz;
    const int m0 = pm << 7;
    const int n0 = pn << 7;

    const int tid  = threadIdx.x;
    const int wid  = tid >> 5;
    const int lane = tid & 31;

    // ------- loader mapping: thread t loads 4x16B of an A row + of a B row
    const int ldr_row  = tid >> 1;
    const int ldr_half = (tid & 1) * 4;
    uint32_t swz[4];
#pragma unroll
    for (int i = 0; i < 4; i++) {
        uint32_t off = (uint32_t)ldr_row * 128 + (ldr_half + i) * 16;
        swz[i] = SMEM_SWIZZLE_128B(off);
    }
    const size_t aoff = (size_t)(m0 + ldr_row) * K + ldr_half * 8;
    const size_t boff = (size_t)(n0 + ldr_row) * K + ldr_half * 8;

    const __nv_bfloat16* segA[3] = {A_hi, A_hi, A_lo};
    const __nv_bfloat16* segB[3] = {B_hi, B_lo, B_hi};

    const int kc = K >> 6;
    const int n_chunks = 3 * kc;

    // ------- compute mapping: warp grid 4(M) x 2(N), warp tile 32x64
    const int warp_m = wid & 3;
    const int warp_n = wid >> 2;
    const int rA = lane & 15;
    const int cA = lane >> 4;
    const uint32_t xorA = (uint32_t)(rA & 7) << 4;
    const uint32_t rowTermA = (uint32_t)(warp_m * 32 + rA) * 128;
    const int rB = (lane & 7) + ((lane >> 4) & 1) * 8;
    const int cB = (lane >> 3) & 1;
    const uint32_t xorB = (uint32_t)(lane & 7) << 4;
    const uint32_t rowTermB = (uint32_t)(warp_n * 64 + rB) * 128;

    float acc[2][8][4];
#pragma unroll
    for (int mt = 0; mt < 2; mt++)
#pragma unroll
        for (int nt = 0; nt < 8; nt++)
#pragma unroll
            for (int i = 0; i < 4; i++) acc[mt][nt][i] = 0.f;

    auto load_stage = [&](int c) {
        const int s = c % STAGES;
        const int seg = c / kc;
        const int k0 = (c - seg * kc) << 6;
        const __nv_bfloat16* gA = segA[seg] + aoff + k0;
        const __nv_bfloat16* gB = segB[seg] + boff + k0;
        const uint32_t dA = tile_base + s * STAGE_BYTES;
        const uint32_t dB = dA + 16384;
#pragma unroll
        for (int i = 0; i < 4; i++) cp_async16(dA + swz[i], gA + i * 8);
#pragma unroll
        for (int i = 0; i < 4; i++) cp_async16(dB + swz[i], gB + i * 8);
        CP_ASYNC_COMMIT();
    };

#pragma unroll
    for (int c = 0; c < STAGES - 1; c++) load_stage(c);

    for (int c = 0; c < n_chunks; c++) {
        if (c + 1 < n_chunks) { CP_ASYNC_WAIT(1); } else { CP_ASYNC_WAIT(0); }
        __syncthreads();   // single barrier per chunk: orders prev compute vs new loads
        if (c + STAGES - 1 < n_chunks) load_stage(c + STAGES - 1);

        const int s = c % STAGES;
        const uint32_t sA = tile_base + s * STAGE_BYTES;
        const uint32_t sB = sA + 16384;

#pragma unroll
        for (int kk = 0; kk < 4; kk++) {
            uint32_t a[2][4];
#pragma unroll
            for (int mt = 0; mt < 2; mt++) {
                uint32_t addr = sA + rowTermA + mt * 2048 +
                                ((((uint32_t)(kk * 2 + cA) << 4)) ^ xorA);
                LDSM_X4(a[mt][0], a[mt][1], a[mt][2], a[mt][3], addr);
            }
            uint32_t b[4][4];
#pragma unroll
            for (int np = 0; np < 4; np++) {
                uint32_t addr = sB + rowTermB + np * 2048 +
                                ((((uint32_t)(kk * 2 + cB) << 4)) ^ xorB);
                LDSM_X4(b[np][0], b[np][1], b[np][2], b[np][3], addr);
            }
#pragma unroll
            for (int mt = 0; mt < 2; mt++)
#pragma unroll
                for (int nt = 0; nt < 8; nt++)
                    mma16816(acc[mt][nt], a[mt],
                             b[nt >> 1][(nt & 1) * 2], b[nt >> 1][(nt & 1) * 2 + 1]);
        }
    }

    // ------- epilogue
    const int egid = lane >> 2;
    const int tig = lane & 3;
    const float ssc = 0.08838834764831845f;  // 1/sqrt(128)

    if (mode == 0) {
#pragma unroll
        for (int mt = 0; mt < 2; mt++) {
#pragma unroll
            for (int nt = 0; nt < 8; nt++) {
                int row = m0 + warp_m * 32 + mt * 16 + egid;
                int col = n0 + warp_n * 64 + nt * 8 + tig * 2;
                *(float2*)(C + (size_t)row * N + col) =
                    make_float2(acc[mt][nt][0], acc[mt][nt][1]);
                *(float2*)(C + (size_t)(row + 8) * N + col) =
                    make_float2(acc[mt][nt][2], acc[mt][nt][3]);
            }
        }
    } else {
        // fused RoPE + bf16 hi/lo split. col layout: [Q|K|V] x (32 heads x 128)
#pragma unroll
        for (int mt = 0; mt < 2; mt++) {
            const int r0 = m0 + warp_m * 32 + mt * 16 + egid;
            const int s0 = r0 & (SEQ - 1);
            const int s1 = (r0 + 8) & (SEQ - 1);
#pragma unroll
            for (int nt = 0; nt < 8; nt++) {
                const int col = n0 + warp_n * 64 + nt * 8 + tig * 2;
                const int qi = col >> 12;          // 0=Q 1=K 2=V
                const int d  = col & 127;
                const int hh = (col >> 7) & 31;
                const int j  = d >> 1;

                float v0 = acc[mt][nt][0], v1 = acc[mt][nt][1];
                float v2 = acc[mt][nt][2], v3 = acc[mt][nt][3];

                if (qi < 2) {
                    const float c0 = fcos[s0 * 64 + j], sn0 = fsin[s0 * 64 + j];
                    const float c1 = fcos[s1 * 64 + j], sn1 = fsin[s1 * 64 + j];
                    const float sc = (qi == 0) ? ssc : 1.f;
                    float o0 = (v0 * c0 - v1 * sn0) * sc;
                    float o1 = (v0 * sn0 + v1 * c0) * sc;
                    float o2 = (v2 * c1 - v3 * sn1) * sc;
                    float o3 = (v2 * sn1 + v3 * c1) * sc;
                    v0 = o0; v1 = o1; v2 = o2; v3 = o3;
                }

                __nv_bfloat16* dh = (qi == 0) ? qh : (qi == 1) ? kh : vh;
                __nv_bfloat16* dl = (qi == 0) ? ql : (qi == 1) ? kl : vl;
                const size_t o0_ = ((size_t)r0 * NHEAD + hh) * HDIM + d;
                const size_t o1_ = o0_ + (size_t)8 * NHEAD * HDIM;

                float h0, l0, h1, l1;
                split_hl(v0, h0, l0); split_hl(v1, h1, l1);
                *(uint32_t*)(dh + o0_) = pack_bf16(h0, h1);
                *(uint32_t*)(dl + o0_) = pack_bf16(l0, l1);
                split_hl(v2, h0, l0); split_hl(v3, h1, l1);
                *(uint32_t*)(dh + o1_) = pack_bf16(h0, h1);
                *(uint32_t*)(dl + o1_) = pack_bf16(l0, l1);
            }
        }
    }
}

// ---------------------------------------------------------------------------
// Tensor-core flash attention (causal). 128 threads = 4 warps, 64 q rows/CTA.
// (unchanged from round 4, verified)
// ---------------------------------------------------------------------------
#define FT_ROWB 272
#define FT_SLOT (64 * FT_ROWB)
#define FT_SMEM (6 * FT_SLOT + 128)

__device__ __forceinline__ void ft_load_tile(
    uint32_t dst, const __nv_bfloat16* __restrict__ g, int grow0, int h, int tid)
{
#pragma unroll
    for (int it = 0; it < 8; it++) {
        int c = tid + it * 128;
        int r = c >> 4, ch = c & 15;
        cp_async16(dst + r * FT_ROWB + ch * 16,
                   g + (size_t)(grow0 + r) * EMB + h * HDIM + ch * 8);
    }
}

__global__ __launch_bounds__(128, 2) void flash_tc(
    const __nv_bfloat16* __restrict__ qh_g, const __nv_bfloat16* __restrict__ ql_g,
    const __nv_bfloat16* __restrict__ kh_g, const __nv_bfloat16* __restrict__ kl_g,
    const __nv_bfloat16* __restrict__ vh_g, const __nv_bfloat16* __restrict__ vl_g,
    __nv_bfloat16* __restrict__ yh_g, __nv_bfloat16* __restrict__ yl_g)
{
    extern __shared__ char sm_raw[];
    const uint32_t base = (smem_to_u32(sm_raw) + 127) & ~127u;
    const uint32_t QH = base, QL = base + FT_SLOT;
    const uint32_t KH = base + 2 * FT_SLOT, KL = base + 3 * FT_SLOT;
    const uint32_t VH = base + 4 * FT_SLOT, VL = base + 5 * FT_SLOT;

    const int tid = threadIdx.x, wid = tid >> 5, lane = tid & 31;
    const int qb = (int)gridDim.x - 1 - (int)blockIdx.x;
    const int bh = blockIdx.y;
    const int b = bh >> 5, h = bh & 31;
    const int q0 = qb * 64;
    const int growq = b * SEQ + q0;

    ft_load_tile(QH, qh_g, growq, h, tid);
    ft_load_tile(QL, ql_g, growq, h, tid);
    CP_ASYNC_COMMIT();
    CP_ASYNC_WAIT(0);
    __syncthreads();

    const int wr = wid * 16;
    const int rA = lane & 15, cA = lane >> 4;
    uint32_t qfh[8][4], qfl[8][4];
#pragma unroll
    for (int kk = 0; kk < 8; kk++) {
        uint32_t ao = (uint32_t)(wr + rA) * FT_ROWB + kk * 32 + cA * 16;
        LDSM_X4(qfh[kk][0], qfh[kk][1], qfh[kk][2], qfh[kk][3], QH + ao);
        LDSM_X4(qfl[kk][0], qfl[kk][1], qfl[kk][2], qfl[kk][3], QL + ao);
    }

    const int rB = (lane & 7) + ((lane >> 4) & 1) * 8;
    const int cB = (lane >> 3) & 1;
    const int vr = lane & 15;
    const int vc = lane >> 4;
    const int egid = lane >> 2, tig = lane & 3;

    float m0 = -1e30f, m1 = -1e30f, l0 = 0.f, l1 = 0.f;
    float accO[16][4];
#pragma unroll
    for (int nt = 0; nt < 16; nt++)
#pragma unroll
        for (int i = 0; i < 4; i++) accO[nt][i] = 0.f;

    for (int t = 0; t <= qb; t++) {
        const int k0 = t * 64;
        const int growk = b * SEQ + k0;
        __syncthreads();
        ft_load_tile(KH, kh_g, growk, h, tid);
        ft_load_tile(KL, kl_g, growk, h, tid);
        ft_load_tile(VH, vh_g, growk, h, tid);
        ft_load_tile(VL, vl_g, growk, h, tid);
        CP_ASYNC_COMMIT();
        CP_ASYNC_WAIT(0);
        __syncthreads();

        float accS[8][4];
#pragma unroll
        for (int nt = 0; nt < 8; nt++)
#pragma unroll
            for (int i = 0; i < 4; i++) accS[nt][i] = 0.f;

#pragma unroll
        for (int kk = 0; kk < 8; kk++) {
            uint32_t bh4[4][4], bl4[4][4];
#pragma unroll
            for (int np = 0; np < 4; np++) {
                uint32_t ao = (uint32_t)(np * 16 + rB) * FT_ROWB + kk * 32 + cB * 16;
                LDSM_X4(bh4[np][0], bh4[np][1], bh4[np][2], bh4[np][3], KH + ao);
                LDSM_X4(bl4[np][0], bl4[np][1], bl4[np][2], bl4[np][3], KL + ao);
            }
#pragma unroll
            for (int np = 0; np < 4; np++)
#pragma unroll
                for (int hf = 0; hf < 2; hf++) {
                    const int nt = np * 2 + hf;
                    mma16816(accS[nt], qfh[kk], bh4[np][hf * 2], bh4[np][hf * 2 + 1]);
                    mma16816(accS[nt], qfl[kk], bh4[np][hf * 2], bh4[np][hf * 2 + 1]);
                    mma16816(accS[nt], qfh[kk], bl4[np][hf * 2], bl4[np][hf * 2 + 1]);
                }
        }

        if (t == qb) {
            const int row0 = wr + egid, row1 = row0 + 8;
#pragma unroll
            for (int nt = 0; nt < 8; nt++) {
                const int c0 = nt * 8 + tig * 2, c1 = c0 + 1;
                if (c0 > row0) accS[nt][0] = -1e30f;
                if (c1 > row0) accS[nt][1] = -1e30f;
                if (c0 > row1) accS[nt][2] = -1e30f;
                if (c1 > row1) accS[nt][3] = -1e30f;
            }
        }

        float mx0 = -1e30f, mx1 = -1e30f;
#pragma unroll
        for (int nt = 0; nt < 8; nt++) {
            mx0 = fmaxf(mx0, fmaxf(accS[nt][0], accS[nt][1]));
            mx1 = fmaxf(mx1, fmaxf(accS[nt][2], accS[nt][3]));
        }
        mx0 = fmaxf(mx0, __shfl_xor_sync(0xffffffffu, mx0, 1));
        mx0 = fmaxf(mx0, __shfl_xor_sync(0xffffffffu, mx0, 2));
        mx1 = fmaxf(mx1, __shfl_xor_sync(0xffffffffu, mx1, 1));
        mx1 = fmaxf(mx1, __shfl_xor_sync(0xffffffffu, mx1, 2));

        const float mn0 = fmaxf(m0, mx0), mn1 = fmaxf(m1, mx1);
        const float a0 = __expf(m0 - mn0), a1 = __expf(m1 - mn1);
        m0 = mn0; m1 = mn1;

        float s0 = 0.f, s1 = 0.f;
#pragma unroll
        for (int nt = 0; nt < 8; nt++) {
            accS[nt][0] = __expf(accS[nt][0] - mn0);
            accS[nt][1] = __expf(accS[nt][1] - mn0);
            accS[nt][2] = __expf(accS[nt][2] - mn1);
            accS[nt][3] = __expf(accS[nt][3] - mn1);
            s0 += accS[nt][0] + accS[nt][1];
            s1 += accS[nt][2] + accS[nt][3];
        }
        s0 += __shfl_xor_sync(0xffffffffu, s0, 1);
        s0 += __shfl_xor_sync(0xffffffffu, s0, 2);
        s1 += __shfl_xor_sync(0xffffffffu, s1, 1);
        s1 += __shfl_xor_sync(0xffffffffu, s1, 2);
        l0 = l0 * a0 + s0;
        l1 = l1 * a1 + s1;

#pragma unroll
        for (int nt = 0; nt < 16; nt++) {
            accO[nt][0] *= a0; accO[nt][1] *= a0;
            accO[nt][2] *= a1; accO[nt][3] *= a1;
        }

        uint32_t pfh[4][4], pfl[4][4];
#pragma unroll
        for (int j = 0; j < 4; j++) {
#pragma unroll
            for (int u = 0; u < 2; u++) {
                const int nt = 2 * j + u;
                float h00, l00, h01, l01, h10, l10, h11, l11;
                split_hl(accS[nt][0], h00, l00);
                split_hl(accS[nt][1], h01, l01);
                split_hl(accS[nt][2], h10, l10);
                split_hl(accS[nt][3], h11, l11);
                pfh[j][u * 2]     = pack_bf16(h00, h01);
                pfh[j][u * 2 + 1] = pack_bf16(h10, h11);
                pfl[j][u * 2]     = pack_bf16(l00, l01);
                pfl[j][u * 2 + 1] = pack_bf16(l10, l11);
            }
        }

#pragma unroll
        for (int j = 0; j < 4; j++) {
#pragma unroll
            for (int np = 0; np < 8; np++) {
                uint32_t vh4[4], vl4[4];
                uint32_t ao = (uint32_t)(j * 16 + vr) * FT_ROWB + np * 32 + vc * 16;
                LDSM_X4_T(vh4[0], vh4[1], vh4[2], vh4[3], VH + ao);
                LDSM_X4_T(vl4[0], vl4[1], vl4[2], vl4[3], VL + ao);
                mma16816(accO[2 * np],     pfh[j], vh4[0], vh4[1]);
                mma16816(accO[2 * np],     pfl[j], vh4[0], vh4[1]);
                mma16816(accO[2 * np],     pfh[j], vl4[0], vl4[1]);
                mma16816(accO[2 * np + 1], pfh[j], vh4[2], vh4[3]);
                mma16816(accO[2 * np + 1], pfl[j], vh4[2], vh4[3]);
                mma16816(accO[2 * np + 1], pfh[j], vl4[2], vl4[3]);
            }
        }
    }

    const float inv0 = 1.f / l0, inv1 = 1.f / l1;
    const size_t row0 = (size_t)(growq + wr + egid);
    const size_t row1 = row0 + 8;
#pragma unroll
    for (int nt = 0; nt < 16; nt++) {
        const int col = h * HDIM + nt * 8 + tig * 2;
        float v0 = accO[nt][0] * inv0, v1 = accO[nt][1] * inv0;
        float v2 = accO[nt][2] * inv1, v3 = accO[nt][3] * inv1;
        float hh, ll, hh2, ll2;
        split_hl(v0, hh, ll); split_hl(v1, hh2, ll2);
        *(uint32_t*)(yh_g + row0 * EMB + col) = pack_bf16(hh, hh2);
        *(uint32_t*)(yl_g + row0 * EMB + col) = pack_bf16(ll, ll2);
        split_hl(v2, hh, ll); split_hl(v3, hh2, ll2);
        *(uint32_t*)(yh_g + row1 * EMB + col) = pack_bf16(hh, hh2);
        *(uint32_t*)(yl_g + row1 * EMB + col) = pack_bf16(ll, ll2);
    }
}

// ---------------------------------------------------------------------------
extern "C" void kernel_launch(void* const* d_in, const int* in_sizes, int n_in,
                              void* d_out, int out_size)
{
    (void)in_sizes; (void)n_in; (void)out_size;
    const float* x       = (const float*)d_in[0];
    const float* w_atten = (const float*)d_in[1];
    const float* w_proj  = (const float*)d_in[2];
    const float* fcos    = (const float*)d_in[3];
    const float* fsin    = (const float*)d_in[4];
    float* out = (float*)d_out;

    __nv_bfloat16 *x_hi, *x_lo, *wa_hi, *wa_lo, *wp_hi, *wp_lo, *y_hi, *y_lo;
    __nv_bfloat16 *q_hi, *q_lo, *k_hi, *k_lo, *v_hi, *v_lo;
    cudaGetSymbolAddress((void**)&x_hi, g_x_hi);
    cudaGetSymbolAddress((void**)&x_lo, g_x_lo);
    cudaGetSymbolAddress((void**)&wa_hi, g_wa_hi);
    cudaGetSymbolAddress((void**)&wa_lo, g_wa_lo);
    cudaGetSymbolAddress((void**)&wp_hi, g_wp_hi);
    cudaGetSymbolAddress((void**)&wp_lo, g_wp_lo);
    cudaGetSymbolAddress((void**)&y_hi, g_y_hi);
    cudaGetSymbolAddress((void**)&y_lo, g_y_lo);
    cudaGetSymbolAddress((void**)&q_hi, g_q_hi);
    cudaGetSymbolAddress((void**)&q_lo, g_q_lo);
    cudaGetSymbolAddress((void**)&k_hi, g_k_hi);
    cudaGetSymbolAddress((void**)&k_lo, g_k_lo);
    cudaGetSymbolAddress((void**)&v_hi, g_v_hi);
    cudaGetSymbolAddress((void**)&v_lo, g_v_lo);

    cudaFuncSetAttribute(tc_gemm, cudaFuncAttributeMaxDynamicSharedMemorySize,
                         GEMM_SMEM);
    cudaFuncSetAttribute(flash_tc, cudaFuncAttributeMaxDynamicSharedMemorySize,
                         FT_SMEM);

    // 1) split x into bf16 hi/lo
    {
        int n4 = MROWS * EMB / 4;
        split_f32_kernel<<<(n4 + 255) / 256, 256>>>(
            (const float4*)x, (uint2*)x_hi, (uint2*)x_lo, n4);
    }
    // 2) split+transpose weights
    split_wT_kernel<<<dim3(QKV_COLS / 32, EMB / 32), dim3(32, 8)>>>(
        w_atten, wa_hi, wa_lo, EMB, QKV_COLS);
    split_wT_kernel<<<dim3(EMB / 32, EMB / 32), dim3(32, 8)>>>(
        w_proj, wp_hi, wp_lo, EMB, EMB);

    // 3) QKV projection + fused RoPE + hi/lo split (HMMA, mode 1)
    tc_gemm<<<(MROWS / 128) * (QKV_COLS / 128), 256, GEMM_SMEM>>>(
        x_hi, x_lo, wa_hi, wa_lo, nullptr, MROWS, QKV_COLS, EMB, 1,
        fcos, fsin, q_hi, q_lo, k_hi, k_lo, v_hi, v_lo);

    // 4) Tensor-core flash attention -> y (bf16 hi/lo)
    {
        dim3 gf(SEQ / 64, BATCH * NHEAD);
        flash_tc<<<gf, 128, FT_SMEM>>>(q_hi, q_lo, k_hi, k_lo, v_hi, v_lo,
                                       y_hi, y_lo);
    }

    // 5) Output projection (HMMA, mode 0)
    tc_gemm<<<(MROWS / 128) * (EMB / 128), 256, GEMM_SMEM>>>(
        y_hi, y_lo, wp_hi, wp_lo, out, MROWS, EMB, EMB, 0,
        nullptr, nullptr, nullptr, nullptr, nullptr, nullptr, nullptr, nullptr);
}

// round 10
// speedup vs baseline: 1.7852x; 1.1761x over previous
#include <cuda_runtime.h>
#include <cuda_bf16.h>
#include <cstdint>
#include <cstddef>

#define BATCH 2
#define SEQ 2048
#define EMB 4096
#define NHEAD 32
#define HDIM 128
#define QKV_COLS (3 * EMB)
#define MROWS (BATCH * SEQ)

// ---------------------------------------------------------------------------
// Scratch (__device__ globals, allocation-free rule)
// ---------------------------------------------------------------------------
__device__ __nv_bfloat16 g_x_hi[(size_t)MROWS * EMB];
__device__ __nv_bfloat16 g_x_lo[(size_t)MROWS * EMB];
__device__ __nv_bfloat16 g_wa_hi[(size_t)QKV_COLS * EMB];  // [N,K] transposed
__device__ __nv_bfloat16 g_wa_lo[(size_t)QKV_COLS * EMB];
__device__ __nv_bfloat16 g_wp_hi[(size_t)EMB * EMB];
__device__ __nv_bfloat16 g_wp_lo[(size_t)EMB * EMB];
__device__ __nv_bfloat16 g_y_hi[(size_t)MROWS * EMB];
__device__ __nv_bfloat16 g_y_lo[(size_t)MROWS * EMB];
// rope-split Q/K/V, [B,S,H,D] bf16
__device__ __nv_bfloat16 g_q_hi[(size_t)MROWS * EMB];
__device__ __nv_bfloat16 g_q_lo[(size_t)MROWS * EMB];
__device__ __nv_bfloat16 g_k_hi[(size_t)MROWS * EMB];
__device__ __nv_bfloat16 g_k_lo[(size_t)MROWS * EMB];
__device__ __nv_bfloat16 g_v_hi[(size_t)MROWS * EMB];
__device__ __nv_bfloat16 g_v_lo[(size_t)MROWS * EMB];

// ---------------------------------------------------------------------------
// PTX helpers (sm_80+ features only: ldmatrix, mma.sync, cp.async)
// ---------------------------------------------------------------------------
__device__ __forceinline__ uint32_t smem_to_u32(const void* smem_ptr) {
    uint32_t addr;
    asm("{ .reg .u64 tmp; cvta.to.shared.u64 tmp, %1; cvt.u32.u64 %0, tmp; }"
        : "=r"(addr) : "l"(smem_ptr));
    return addr;
}

#define SMEM_SWIZZLE_128B(byte_offset) \
    ((byte_offset) ^ (((byte_offset) >> 3) & 0x70))
#define SMEM_SWIZZLE_64B(byte_offset) \
    ((byte_offset) ^ (((byte_offset) >> 3) & 0x30))

__device__ __forceinline__ void cp_async16(uint32_t dst, const void* src) {
    asm volatile("cp.async.cg.shared.global [%0], [%1], 16;"
                 :: "r"(dst), "l"(src) : "memory");
}
#define CP_ASYNC_COMMIT() asm volatile("cp.async.commit_group;" ::: "memory")
#define CP_ASYNC_WAIT(n)  asm volatile("cp.async.wait_group %0;" :: "n"(n) : "memory")

#define LDSM_X4(r0, r1, r2, r3, addr) \
    asm volatile("ldmatrix.sync.aligned.m8n8.x4.shared.b16 {%0,%1,%2,%3}, [%4];" \
                 : "=r"(r0), "=r"(r1), "=r"(r2), "=r"(r3) : "r"(addr))

#define LDSM_X4_T(r0, r1, r2, r3, addr) \
    asm volatile("ldmatrix.sync.aligned.m8n8.x4.trans.shared.b16 {%0,%1,%2,%3}, [%4];" \
                 : "=r"(r0), "=r"(r1), "=r"(r2), "=r"(r3) : "r"(addr))

__device__ __forceinline__ void mma16816(float* c, const uint32_t* a,
                                         uint32_t b0, uint32_t b1) {
    asm volatile(
        "mma.sync.aligned.m16n8k16.row.col.f32.bf16.bf16.f32 "
        "{%0,%1,%2,%3}, {%4,%5,%6,%7}, {%8,%9}, {%0,%1,%2,%3};"
        : "+f"(c[0]), "+f"(c[1]), "+f"(c[2]), "+f"(c[3])
        : "r"(a[0]), "r"(a[1]), "r"(a[2]), "r"(a[3]), "r"(b0), "r"(b1));
}

// pack two floats to bf16x2 (first -> low half, second -> high half)
__device__ __forceinline__ uint32_t pack_bf16(float lo, float hi) {
    return (uint32_t)__bfloat16_as_ushort(__float2bfloat16(lo)) |
           ((uint32_t)__bfloat16_as_ushort(__float2bfloat16(hi)) << 16);
}
// split one float into bf16 hi and residual-lo floats
__device__ __forceinline__ void split_hl(float v, float& h, float& l) {
    h = __bfloat162float(__float2bfloat16(v));
    l = v - h;
}

// ---------------------------------------------------------------------------
// Split fp32 -> bf16 hi/lo (elementwise, vectorized)
// ---------------------------------------------------------------------------
__global__ __launch_bounds__(256) void split_f32_kernel(
    const float4* __restrict__ in, uint2* __restrict__ hi, uint2* __restrict__ lo, int n4)
{
    int i = blockIdx.x * 256 + threadIdx.x;
    if (i >= n4) return;
    float4 v = in[i];
    float f[4] = {v.x, v.y, v.z, v.w};
    uint32_t hw[2] = {0, 0}, lw[2] = {0, 0};
#pragma unroll
    for (int j = 0; j < 4; j++) {
        __nv_bfloat16 h = __float2bfloat16(f[j]);
        __nv_bfloat16 l = __float2bfloat16(f[j] - __bfloat162float(h));
        hw[j >> 1] |= ((uint32_t)__bfloat16_as_ushort(h)) << ((j & 1) * 16);
        lw[j >> 1] |= ((uint32_t)__bfloat16_as_ushort(l)) << ((j & 1) * 16);
    }
    hi[i] = make_uint2(hw[0], hw[1]);
    lo[i] = make_uint2(lw[0], lw[1]);
}

// ---------------------------------------------------------------------------
// Split + transpose weights: w [K,N] fp32 (row-major) -> hiT/loT [N,K] bf16
// ---------------------------------------------------------------------------
__global__ __launch_bounds__(256) void split_wT_kernel(
    const float* __restrict__ w, __nv_bfloat16* __restrict__ hiT,
    __nv_bfloat16* __restrict__ loT, int K, int N)
{
    __shared__ float t[32][33];
    const int bx = blockIdx.x;   // N tile
    const int by = blockIdx.y;   // K tile
    const int tx = threadIdx.x;  // 0..31
    const int ty = threadIdx.y;  // 0..7
#pragma unroll
    for (int i = 0; i < 4; i++)
        t[ty + 8 * i][tx] = w[(size_t)(by * 32 + ty + 8 * i) * N + bx * 32 + tx];
    __syncthreads();
#pragma unroll
    for (int i = 0; i < 4; i++) {
        int nn = ty + 8 * i;
        float v = t[tx][nn];
        __nv_bfloat16 h = __float2bfloat16(v);
        __nv_bfloat16 l = __float2bfloat16(v - __bfloat162float(h));
        size_t o = (size_t)(bx * 32 + nn) * K + by * 32 + tx;
        hiT[o] = h;
        loT[o] = l;
    }
}

// ---------------------------------------------------------------------------
// HMMA bf16 split-GEMM with cross-segment operand sharing.
// CTA tile 128x128, 8 warps (4x2), warp tile 32x64, BK=32.
// Each stage holds Ah|Al|Bh|Bl (128x32 bf16 = 8KB each, 64B rows, SW64).
// Per k-step: MMA(Ah,Bh) + MMA(Al,Bh) + MMA(Ah,Bl) with shared fragments
// (B register array reused for Bh then Bl). 1.5x less smem traffic/FLOP.
// mode 0: fp32 C.  mode 1 (QKV): fused RoPE + bf16 hi/lo split of Q/K/V.
// ---------------------------------------------------------------------------
#define STAGES 3
#define STAGE_BYTES 32768
#define OFF_AH 0
#define OFF_AL 8192
#define OFF_BH 16384
#define OFF_BL 24576
#define GEMM_SMEM (1024 + STAGES * STAGE_BYTES)

__global__ __launch_bounds__(256, 2) void tc_gemm(
    const __nv_bfloat16* __restrict__ A_hi, const __nv_bfloat16* __restrict__ A_lo,
    const __nv_bfloat16* __restrict__ B_hi, const __nv_bfloat16* __restrict__ B_lo,
    float* __restrict__ C, int M, int N, int K, int mode,
    const float* __restrict__ fcos, const float* __restrict__ fsin,
    __nv_bfloat16* __restrict__ qh, __nv_bfloat16* __restrict__ ql,
    __nv_bfloat16* __restrict__ kh, __nv_bfloat16* __restrict__ kl,
    __nv_bfloat16* __restrict__ vh, __nv_bfloat16* __restrict__ vl)
{
    extern __shared__ char smem_raw[];
    const uint32_t smem_base = smem_to_u32(smem_raw);
    const uint32_t tile_base = (smem_base + 1023) & ~1023u;

    const int tiles_m = M >> 7;
    const int tiles_n = N >> 7;

    // grouped raster for L2 reuse
    const int G = 8;
    int pid = blockIdx.x;
    int npg = G * tiles_n;
    int gid_g = pid / npg;
    int first_m = gid_g * G;
    int gsz = tiles_m - first_m;
    if (gsz > G) gsz = G;
    int pm = first_m + (pid % gsz);
    int pn = (pid % npg) / gsz;
    const int m0 = pm << 7;
    const int n0 = pn << 7;

    const int tid  = threadIdx.x;
    const int wid  = tid >> 5;
    const int lane = tid & 31;

    // ------- loader mapping: thread t owns one row of each tile, 2x16B chunks
    const int ldr_row = tid >> 1;           // 0..127
    const int ldr_c   = (tid & 1) * 2;      // chunk base 0 or 2 (16B units)
    uint32_t swz[2];
#pragma unroll
    for (int i = 0; i < 2; i++)
        swz[i] = SMEM_SWIZZLE_64B((uint32_t)(ldr_row * 64 + (ldr_c + i) * 16));
    const size_t aoff = (size_t)(m0 + ldr_row) * K + ldr_c * 8;
    const size_t boff = (size_t)(n0 + ldr_row) * K + ldr_c * 8;

    const int kc = K >> 5;                  // BK=32 chunks

    auto load_stage = [&](int c) {
        const int s = c % STAGES;
        const int k0 = c << 5;
        const uint32_t st = tile_base + s * STAGE_BYTES;
        const __nv_bfloat16* gAh = A_hi + aoff + k0;
        const __nv_bfloat16* gAl = A_lo + aoff + k0;
        const __nv_bfloat16* gBh = B_hi + boff + k0;
        const __nv_bfloat16* gBl = B_lo + boff + k0;
#pragma unroll
        for (int i = 0; i < 2; i++) {
            cp_async16(st + OFF_AH + swz[i], gAh + i * 8);
            cp_async16(st + OFF_AL + swz[i], gAl + i * 8);
            cp_async16(st + OFF_BH + swz[i], gBh + i * 8);
            cp_async16(st + OFF_BL + swz[i], gBl + i * 8);
        }
        CP_ASYNC_COMMIT();
    };

    // ------- compute mapping: warp grid 4(M) x 2(N), warp tile 32x64
    const int warp_m = wid & 3;
    const int warp_n = wid >> 2;
    const int rA = lane & 15;
    const int cA = lane >> 4;               // 0/1 -> 16B chunk
    const uint32_t xorA = (uint32_t)((rA >> 1) & 3) << 4;
    const uint32_t rowTermA = (uint32_t)(warp_m * 32 + rA) * 64;
    const int rB = (lane & 7) + ((lane >> 4) & 1) * 8;
    const int cB = (lane >> 3) & 1;
    const uint32_t xorB = (uint32_t)((rB >> 1) & 3) << 4;
    const uint32_t rowTermB = (uint32_t)(warp_n * 64 + rB) * 64;

    float acc[2][8][4];
#pragma unroll
    for (int mt = 0; mt < 2; mt++)
#pragma unroll
        for (int nt = 0; nt < 8; nt++)
#pragma unroll
            for (int i = 0; i < 4; i++) acc[mt][nt][i] = 0.f;

#pragma unroll
    for (int c = 0; c < STAGES - 1; c++) load_stage(c);

    for (int c = 0; c < kc; c++) {
        if (c + 1 < kc) { CP_ASYNC_WAIT(1); } else { CP_ASYNC_WAIT(0); }
        __syncthreads();
        if (c + STAGES - 1 < kc) load_stage(c + STAGES - 1);

        const uint32_t st = tile_base + (c % STAGES) * STAGE_BYTES;

#pragma unroll
        for (int kk = 0; kk < 2; kk++) {
            const uint32_t colA = ((uint32_t)(kk * 32 + cA * 16)) ^ xorA;
            const uint32_t colB = ((uint32_t)(kk * 32 + cB * 16)) ^ xorB;

            uint32_t ah[2][4], al[2][4], b[4][4];
            // B_hi fragments
#pragma unroll
            for (int np = 0; np < 4; np++)
                LDSM_X4(b[np][0], b[np][1], b[np][2], b[np][3],
                        st + OFF_BH + rowTermB + np * 1024 + colB);
            // A_hi fragments
#pragma unroll
            for (int mt = 0; mt < 2; mt++)
                LDSM_X4(ah[mt][0], ah[mt][1], ah[mt][2], ah[mt][3],
                        st + OFF_AH + rowTermA + mt * 1024 + colA);
            // pass 1: Ah * Bh
#pragma unroll
            for (int mt = 0; mt < 2; mt++)
#pragma unroll
                for (int nt = 0; nt < 8; nt++)
                    mma16816(acc[mt][nt], ah[mt],
                             b[nt >> 1][(nt & 1) * 2], b[nt >> 1][(nt & 1) * 2 + 1]);
            // A_lo fragments
#pragma unroll
            for (int mt = 0; mt < 2; mt++)
                LDSM_X4(al[mt][0], al[mt][1], al[mt][2], al[mt][3],
                        st + OFF_AL + rowTermA + mt * 1024 + colA);
            // pass 2: Al * Bh
#pragma unroll
            for (int mt = 0; mt < 2; mt++)
#pragma unroll
                for (int nt = 0; nt < 8; nt++)
                    mma16816(acc[mt][nt], al[mt],
                             b[nt >> 1][(nt & 1) * 2], b[nt >> 1][(nt & 1) * 2 + 1]);
            // B_lo fragments (reuse b registers)
#pragma unroll
            for (int np = 0; np < 4; np++)
                LDSM_X4(b[np][0], b[np][1], b[np][2], b[np][3],
                        st + OFF_BL + rowTermB + np * 1024 + colB);
            // pass 3: Ah * Bl
#pragma unroll
            for (int mt = 0; mt < 2; mt++)
#pragma unroll
                for (int nt = 0; nt < 8; nt++)
                    mma16816(acc[mt][nt], ah[mt],
                             b[nt >> 1][(nt & 1) * 2], b[nt >> 1][(nt & 1) * 2 + 1]);
        }
    }

    // ------- epilogue
    const int egid = lane >> 2;
    const int tig = lane & 3;
    const float ssc = 0.08838834764831845f;  // 1/sqrt(128)

    if (mode == 0) {
#pragma unroll
        for (int mt = 0; mt < 2; mt++) {
#pragma unroll
            for (int nt = 0; nt < 8; nt++) {
                int row = m0 + warp_m * 32 + mt * 16 + egid;
                int col = n0 + warp_n * 64 + nt * 8 + tig * 2;
                *(float2*)(C + (size_t)row * N + col) =
                    make_float2(acc[mt][nt][0], acc[mt][nt][1]);
                *(float2*)(C + (size_t)(row + 8) * N + col) =
                    make_float2(acc[mt][nt][2], acc[mt][nt][3]);
            }
        }
    } else {
        // fused RoPE + bf16 hi/lo split. col layout: [Q|K|V] x (32 heads x 128)
#pragma unroll
        for (int mt = 0; mt < 2; mt++) {
            const int r0 = m0 + warp_m * 32 + mt * 16 + egid;
            const int s0 = r0 & (SEQ - 1);
            const int s1 = (r0 + 8) & (SEQ - 1);
#pragma unroll
            for (int nt = 0; nt < 8; nt++) {
                const int col = n0 + warp_n * 64 + nt * 8 + tig * 2;
                const int qi = col >> 12;          // 0=Q 1=K 2=V
                const int d  = col & 127;
                const int hh = (col >> 7) & 31;
                const int j  = d >> 1;

                float v0 = acc[mt][nt][0], v1 = acc[mt][nt][1];
                float v2 = acc[mt][nt][2], v3 = acc[mt][nt][3];

                if (qi < 2) {
                    const float c0 = fcos[s0 * 64 + j], sn0 = fsin[s0 * 64 + j];
                    const float c1 = fcos[s1 * 64 + j], sn1 = fsin[s1 * 64 + j];
                    const float sc = (qi == 0) ? ssc : 1.f;
                    float o0 = (v0 * c0 - v1 * sn0) * sc;
                    float o1 = (v0 * sn0 + v1 * c0) * sc;
                    float o2 = (v2 * c1 - v3 * sn1) * sc;
                    float o3 = (v2 * sn1 + v3 * c1) * sc;
                    v0 = o0; v1 = o1; v2 = o2; v3 = o3;
                }

                __nv_bfloat16* dh = (qi == 0) ? qh : (qi == 1) ? kh : vh;
                __nv_bfloat16* dl = (qi == 0) ? ql : (qi == 1) ? kl : vl;
                const size_t o0_ = ((size_t)r0 * NHEAD + hh) * HDIM + d;
                const size_t o1_ = o0_ + (size_t)8 * NHEAD * HDIM;

                float h0, l0, h1, l1;
                split_hl(v0, h0, l0); split_hl(v1, h1, l1);
                *(uint32_t*)(dh + o0_) = pack_bf16(h0, h1);
                *(uint32_t*)(dl + o0_) = pack_bf16(l0, l1);
                split_hl(v2, h0, l0); split_hl(v3, h1, l1);
                *(uint32_t*)(dh + o1_) = pack_bf16(h0, h1);
                *(uint32_t*)(dl + o1_) = pack_bf16(l0, l1);
            }
        }
    }
}

// ---------------------------------------------------------------------------
// Tensor-core flash attention (causal). 128 threads = 4 warps, 64 q rows/CTA.
// (unchanged from round 4, verified)
// ---------------------------------------------------------------------------
#define FT_ROWB 272
#define FT_SLOT (64 * FT_ROWB)
#define FT_SMEM (6 * FT_SLOT + 128)

__device__ __forceinline__ void ft_load_tile(
    uint32_t dst, const __nv_bfloat16* __restrict__ g, int grow0, int h, int tid)
{
#pragma unroll
    for (int it = 0; it < 8; it++) {
        int c = tid + it * 128;
        int r = c >> 4, ch = c & 15;
        cp_async16(dst + r * FT_ROWB + ch * 16,
                   g + (size_t)(grow0 + r) * EMB + h * HDIM + ch * 8);
    }
}

__global__ __launch_bounds__(128, 2) void flash_tc(
    const __nv_bfloat16* __restrict__ qh_g, const __nv_bfloat16* __restrict__ ql_g,
    const __nv_bfloat16* __restrict__ kh_g, const __nv_bfloat16* __restrict__ kl_g,
    const __nv_bfloat16* __restrict__ vh_g, const __nv_bfloat16* __restrict__ vl_g,
    __nv_bfloat16* __restrict__ yh_g, __nv_bfloat16* __restrict__ yl_g)
{
    extern __shared__ char sm_raw[];
    const uint32_t base = (smem_to_u32(sm_raw) + 127) & ~127u;
    const uint32_t QH = base, QL = base + FT_SLOT;
    const uint32_t KH = base + 2 * FT_SLOT, KL = base + 3 * FT_SLOT;
    const uint32_t VH = base + 4 * FT_SLOT, VL = base + 5 * FT_SLOT;

    const int tid = threadIdx.x, wid = tid >> 5, lane = tid & 31;
    const int qb = (int)gridDim.x - 1 - (int)blockIdx.x;
    const int bh = blockIdx.y;
    const int b = bh >> 5, h = bh & 31;
    const int q0 = qb * 64;
    const int growq = b * SEQ + q0;

    ft_load_tile(QH, qh_g, growq, h, tid);
    ft_load_tile(QL, ql_g, growq, h, tid);
    CP_ASYNC_COMMIT();
    CP_ASYNC_WAIT(0);
    __syncthreads();

    const int wr = wid * 16;
    const int rA = lane & 15, cA = lane >> 4;
    uint32_t qfh[8][4], qfl[8][4];
#pragma unroll
    for (int kk = 0; kk < 8; kk++) {
        uint32_t ao = (uint32_t)(wr + rA) * FT_ROWB + kk * 32 + cA * 16;
        LDSM_X4(qfh[kk][0], qfh[kk][1], qfh[kk][2], qfh[kk][3], QH + ao);
        LDSM_X4(qfl[kk][0], qfl[kk][1], qfl[kk][2], qfl[kk][3], QL + ao);
    }

    const int rB = (lane & 7) + ((lane >> 4) & 1) * 8;
    const int cB = (lane >> 3) & 1;
    const int vr = lane & 15;
    const int vc = lane >> 4;
    const int egid = lane >> 2, tig = lane & 3;

    float m0 = -1e30f, m1 = -1e30f, l0 = 0.f, l1 = 0.f;
    float accO[16][4];
#pragma unroll
    for (int nt = 0; nt < 16; nt++)
#pragma unroll
        for (int i = 0; i < 4; i++) accO[nt][i] = 0.f;

    for (int t = 0; t <= qb; t++) {
        const int k0 = t * 64;
        const int growk = b * SEQ + k0;
        __syncthreads();
        ft_load_tile(KH, kh_g, growk, h, tid);
        ft_load_tile(KL, kl_g, growk, h, tid);
        ft_load_tile(VH, vh_g, growk, h, tid);
        ft_load_tile(VL, vl_g, growk, h, tid);
        CP_ASYNC_COMMIT();
        CP_ASYNC_WAIT(0);
        __syncthreads();

        float accS[8][4];
#pragma unroll
        for (int nt = 0; nt < 8; nt++)
#pragma unroll
            for (int i = 0; i < 4; i++) accS[nt][i] = 0.f;

#pragma unroll
        for (int kk = 0; kk < 8; kk++) {
            uint32_t bh4[4][4], bl4[4][4];
#pragma unroll
            for (int np = 0; np < 4; np++) {
                uint32_t ao = (uint32_t)(np * 16 + rB) * FT_ROWB + kk * 32 + cB * 16;
                LDSM_X4(bh4[np][0], bh4[np][1], bh4[np][2], bh4[np][3], KH + ao);
                LDSM_X4(bl4[np][0], bl4[np][1], bl4[np][2], bl4[np][3], KL + ao);
            }
#pragma unroll
            for (int np = 0; np < 4; np++)
#pragma unroll
                for (int hf = 0; hf < 2; hf++) {
                    const int nt = np * 2 + hf;
                    mma16816(accS[nt], qfh[kk], bh4[np][hf * 2], bh4[np][hf * 2 + 1]);
                    mma16816(accS[nt], qfl[kk], bh4[np][hf * 2], bh4[np][hf * 2 + 1]);
                    mma16816(accS[nt], qfh[kk], bl4[np][hf * 2], bl4[np][hf * 2 + 1]);
                }
        }

        if (t == qb) {
            const int row0 = wr + egid, row1 = row0 + 8;
#pragma unroll
            for (int nt = 0; nt < 8; nt++) {
                const int c0 = nt * 8 + tig * 2, c1 = c0 + 1;
                if (c0 > row0) accS[nt][0] = -1e30f;
                if (c1 > row0) accS[nt][1] = -1e30f;
                if (c0 > row1) accS[nt][2] = -1e30f;
                if (c1 > row1) accS[nt][3] = -1e30f;
            }
        }

        float mx0 = -1e30f, mx1 = -1e30f;
#pragma unroll
        for (int nt = 0; nt < 8; nt++) {
            mx0 = fmaxf(mx0, fmaxf(accS[nt][0], accS[nt][1]));
            mx1 = fmaxf(mx1, fmaxf(accS[nt][2], accS[nt][3]));
        }
        mx0 = fmaxf(mx0, __shfl_xor_sync(0xffffffffu, mx0, 1));
        mx0 = fmaxf(mx0, __shfl_xor_sync(0xffffffffu, mx0, 2));
        mx1 = fmaxf(mx1, __shfl_xor_sync(0xffffffffu, mx1, 1));
        mx1 = fmaxf(mx1, __shfl_xor_sync(0xffffffffu, mx1, 2));

        const float mn0 = fmaxf(m0, mx0), mn1 = fmaxf(m1, mx1);
        const float a0 = __expf(m0 - mn0), a1 = __expf(m1 - mn1);
        m0 = mn0; m1 = mn1;

        float s0 = 0.f, s1 = 0.f;
#pragma unroll
        for (int nt = 0; nt < 8; nt++) {
            accS[nt][0] = __expf(accS[nt][0] - mn0);
            accS[nt][1] = __expf(accS[nt][1] - mn0);
            accS[nt][2] = __expf(accS[nt][2] - mn1);
            accS[nt][3] = __expf(accS[nt][3] - mn1);
            s0 += accS[nt][0] + accS[nt][1];
            s1 += accS[nt][2] + accS[nt][3];
        }
        s0 += __shfl_xor_sync(0xffffffffu, s0, 1);
        s0 += __shfl_xor_sync(0xffffffffu, s0, 2);
        s1 += __shfl_xor_sync(0xffffffffu, s1, 1);
        s1 += __shfl_xor_sync(0xffffffffu, s1, 2);
        l0 = l0 * a0 + s0;
        l1 = l1 * a1 + s1;

#pragma unroll
        for (int nt = 0; nt < 16; nt++) {
            accO[nt][0] *= a0; accO[nt][1] *= a0;
            accO[nt][2] *= a1; accO[nt][3] *= a1;
        }

        uint32_t pfh[4][4], pfl[4][4];
#pragma unroll
        for (int j = 0; j < 4; j++) {
#pragma unroll
            for (int u = 0; u < 2; u++) {
                const int nt = 2 * j + u;
                float h00, l00, h01, l01, h10, l10, h11, l11;
                split_hl(accS[nt][0], h00, l00);
                split_hl(accS[nt][1], h01, l01);
                split_hl(accS[nt][2], h10, l10);
                split_hl(accS[nt][3], h11, l11);
                pfh[j][u * 2]     = pack_bf16(h00, h01);
                pfh[j][u * 2 + 1] = pack_bf16(h10, h11);
                pfl[j][u * 2]     = pack_bf16(l00, l01);
                pfl[j][u * 2 + 1] = pack_bf16(l10, l11);
            }
        }

#pragma unroll
        for (int j = 0; j < 4; j++) {
#pragma unroll
            for (int np = 0; np < 8; np++) {
                uint32_t vh4[4], vl4[4];
                uint32_t ao = (uint32_t)(j * 16 + vr) * FT_ROWB + np * 32 + vc * 16;
                LDSM_X4_T(vh4[0], vh4[1], vh4[2], vh4[3], VH + ao);
                LDSM_X4_T(vl4[0], vl4[1], vl4[2], vl4[3], VL + ao);
                mma16816(accO[2 * np],     pfh[j], vh4[0], vh4[1]);
                mma16816(accO[2 * np],     pfl[j], vh4[0], vh4[1]);
                mma16816(accO[2 * np],     pfh[j], vl4[0], vl4[1]);
                mma16816(accO[2 * np + 1], pfh[j], vh4[2], vh4[3]);
                mma16816(accO[2 * np + 1], pfl[j], vh4[2], vh4[3]);
                mma16816(accO[2 * np + 1], pfh[j], vl4[2], vl4[3]);
            }
        }
    }

    const float inv0 = 1.f / l0, inv1 = 1.f / l1;
    const size_t row0 = (size_t)(growq + wr + egid);
    const size_t row1 = row0 + 8;
#pragma unroll
    for (int nt = 0; nt < 16; nt++) {
        const int col = h * HDIM + nt * 8 + tig * 2;
        float v0 = accO[nt][0] * inv0, v1 = accO[nt][1] * inv0;
        float v2 = accO[nt][2] * inv1, v3 = accO[nt][3] * inv1;
        float hh, ll, hh2, ll2;
        split_hl(v0, hh, ll); split_hl(v1, hh2, ll2);
        *(uint32_t*)(yh_g + row0 * EMB + col) = pack_bf16(hh, hh2);
        *(uint32_t*)(yl_g + row0 * EMB + col) = pack_bf16(ll, ll2);
        split_hl(v2, hh, ll); split_hl(v3, hh2, ll2);
        *(uint32_t*)(yh_g + row1 * EMB + col) = pack_bf16(hh, hh2);
        *(uint32_t*)(yl_g + row1 * EMB + col) = pack_bf16(ll, ll2);
    }
}

// ---------------------------------------------------------------------------
extern "C" void kernel_launch(void* const* d_in, const int* in_sizes, int n_in,
                              void* d_out, int out_size)
{
    (void)in_sizes; (void)n_in; (void)out_size;
    const float* x       = (const float*)d_in[0];
    const float* w_atten = (const float*)d_in[1];
    const float* w_proj  = (const float*)d_in[2];
    const float* fcos    = (const float*)d_in[3];
    const float* fsin    = (const float*)d_in[4];
    float* out = (float*)d_out;

    __nv_bfloat16 *x_hi, *x_lo, *wa_hi, *wa_lo, *wp_hi, *wp_lo, *y_hi, *y_lo;
    __nv_bfloat16 *q_hi, *q_lo, *k_hi, *k_lo, *v_hi, *v_lo;
    cudaGetSymbolAddress((void**)&x_hi, g_x_hi);
    cudaGetSymbolAddress((void**)&x_lo, g_x_lo);
    cudaGetSymbolAddress((void**)&wa_hi, g_wa_hi);
    cudaGetSymbolAddress((void**)&wa_lo, g_wa_lo);
    cudaGetSymbolAddress((void**)&wp_hi, g_wp_hi);
    cudaGetSymbolAddress((void**)&wp_lo, g_wp_lo);
    cudaGetSymbolAddress((void**)&y_hi, g_y_hi);
    cudaGetSymbolAddress((void**)&y_lo, g_y_lo);
    cudaGetSymbolAddress((void**)&q_hi, g_q_hi);
    cudaGetSymbolAddress((void**)&q_lo, g_q_lo);
    cudaGetSymbolAddress((void**)&k_hi, g_k_hi);
    cudaGetSymbolAddress((void**)&k_lo, g_k_lo);
    cudaGetSymbolAddress((void**)&v_hi, g_v_hi);
    cudaGetSymbolAddress((void**)&v_lo, g_v_lo);

    cudaFuncSetAttribute(tc_gemm, cudaFuncAttributeMaxDynamicSharedMemorySize,
                         GEMM_SMEM);
    cudaFuncSetAttribute(flash_tc, cudaFuncAttributeMaxDynamicSharedMemorySize,
                         FT_SMEM);

    // 1) split x into bf16 hi/lo
    {
        int n4 = MROWS * EMB / 4;
        split_f32_kernel<<<(n4 + 255) / 256, 256>>>(
            (const float4*)x, (uint2*)x_hi, (uint2*)x_lo, n4);
    }
    // 2) split+transpose weights
    split_wT_kernel<<<dim3(QKV_COLS / 32, EMB / 32), dim3(32, 8)>>>(
        w_atten, wa_hi, wa_lo, EMB, QKV_COLS);
    split_wT_kernel<<<dim3(EMB / 32, EMB / 32), dim3(32, 8)>>>(
        w_proj, wp_hi, wp_lo, EMB, EMB);

    // 3) QKV projection + fused RoPE + hi/lo split (HMMA, mode 1)
    tc_gemm<<<(MROWS / 128) * (QKV_COLS / 128), 256, GEMM_SMEM>>>(
        x_hi, x_lo, wa_hi, wa_lo, nullptr, MROWS, QKV_COLS, EMB, 1,
        fcos, fsin, q_hi, q_lo, k_hi, k_lo, v_hi, v_lo);

    // 4) Tensor-core flash attention -> y (bf16 hi/lo)
    {
        dim3 gf(SEQ / 64, BATCH * NHEAD);
        flash_tc<<<gf, 128, FT_SMEM>>>(q_hi, q_lo, k_hi, k_lo, v_hi, v_lo,
                                       y_hi, y_lo);
    }

    // 5) Output projection (HMMA, mode 0)
    tc_gemm<<<(MROWS / 128) * (EMB / 128), 256, GEMM_SMEM>>>(
        y_hi, y_lo, wp_hi, wp_lo, out, MROWS, EMB, EMB, 0,
        nullptr, nullptr, nullptr, nullptr, nullptr, nullptr, nullptr, nullptr);
}